// round 2
// baseline (speedup 1.0000x reference)
#include <cuda_runtime.h>
#include <math.h>

// Problem constants: shape (2,3,128,128,128) fp32
#define NTOT   (12582912)      // 6 << 21
#define ALPHA  0.001
#define EPSF   1e-8f

static __device__ double g_acc[3];   // [0]=region_in, [1]=region_out, [2]=elastica(curv part)

__global__ void ace_zero() {
    g_acc[0] = 0.0; g_acc[1] = 0.0; g_acc[2] = 0.0;
}

__global__ __launch_bounds__(256) void ace_main(
    const float* __restrict__ yp, const float* __restrict__ yt)
{
    const int idx = blockIdx.x * blockDim.x + threadIdx.x;

    float a_in = 0.f, a_out = 0.f, a_el = 0.f;

    if (idx < NTOT) {
        // decompose: x fastest (axis4), then y (axis3), z (axis2), volume (b*c)
        const int x = idx & 127;
        const int y = (idx >> 7) & 127;
        const int z = (idx >> 14) & 127;
        const float* __restrict__ U = yp + (size_t)((idx >> 21) << 21);

        const int xm = x > 0 ? x - 1 : 0;
        const int xp = x < 127 ? x + 1 : 127;
        const int ym = y > 0 ? y - 1 : 0;
        const int yp_ = y < 127 ? y + 1 : 127;
        const int zm = z > 0 ? z - 1 : 0;
        const int zp = z < 127 ? z + 1 : 127;

        #define AT(zz,yy,xx) __ldg(U + (((zz) << 14) + ((yy) << 7) + (xx)))

        const float uc  = AT(z,  y,   x);
        const float uzm = AT(zm, y,   x);
        const float uzp = AT(zp, y,   x);
        const float uym = AT(z,  ym,  x);
        const float uyp = AT(z,  yp_, x);
        const float uxm = AT(z,  y,   xm);
        const float uxp = AT(z,  y,   xp);

        // first derivatives (i=z axis2, j=y axis3, k=x axis4)
        const float ci = 0.5f * (uzp - uzm);
        const float cj = 0.5f * (uyp - uym);
        const float ck = 0.5f * (uxp - uxm);

        // second derivatives (clamped form matches boundary formulas exactly)
        const float cii = uzp + uzm - 2.f * uc;
        const float cjj = uyp + uym - 2.f * uc;
        const float ckk = uxp + uxm - 2.f * uc;

        // mixed derivatives: mixed(c)[i] = c[clamp(i+1)] - c[clamp(i-1)], no /2
        const float cij = 0.5f * ((AT(zp, yp_, x) - AT(zm, yp_, x))
                                - (AT(zp, ym,  x) - AT(zm, ym,  x)));
        const float cik = 0.5f * ((AT(zp, y, xp)  - AT(zm, y, xp))
                                - (AT(zp, y, xm)  - AT(zm, y, xm)));
        const float cjk = 0.5f * ((AT(z, yp_, xp) - AT(z, ym, xp))
                                - (AT(z, yp_, xm) - AT(z, ym, xm)));
        #undef AT

        const float ci2 = ci * ci, cj2 = cj * cj, ck2 = ck * ck;
        const float s   = ci2 + cj2 + ck2;
        const float length = sqrtf(EPSF + s);
        float curv = (1.f + ci2 + cj2) * ckk
                   + (1.f + cj2 + ck2) * cii
                   + (1.f + ci2 + ck2) * cjj
                   - 2.f * cik * cjk * cij;
        const float denom = sqrtf(1.f + s) + EPSF;
        const float c = fabsf(curv) / denom;
        a_el = c * c * length;           // BETA=1; ALPHA added analytically

        const float t = __ldg(yt + idx);
        a_in  = uc * (t - 1.f) * (t - 1.f);
        a_out = (1.f - uc) * t * t;
    }

    // ---- block reduction (3 accumulators) ----
    const unsigned FULL = 0xFFFFFFFFu;
    #pragma unroll
    for (int o = 16; o > 0; o >>= 1) {
        a_in  += __shfl_down_sync(FULL, a_in,  o);
        a_out += __shfl_down_sync(FULL, a_out, o);
        a_el  += __shfl_down_sync(FULL, a_el,  o);
    }

    __shared__ float s_in[8], s_out[8], s_el[8];
    const int lane = threadIdx.x & 31, wid = threadIdx.x >> 5;
    if (lane == 0) { s_in[wid] = a_in; s_out[wid] = a_out; s_el[wid] = a_el; }
    __syncthreads();

    if (wid == 0) {
        a_in  = (lane < 8) ? s_in[lane]  : 0.f;
        a_out = (lane < 8) ? s_out[lane] : 0.f;
        a_el  = (lane < 8) ? s_el[lane]  : 0.f;
        #pragma unroll
        for (int o = 4; o > 0; o >>= 1) {
            a_in  += __shfl_down_sync(FULL, a_in,  o);
            a_out += __shfl_down_sync(FULL, a_out, o);
            a_el  += __shfl_down_sync(FULL, a_el,  o);
        }
        if (lane == 0) {
            atomicAdd(&g_acc[0], (double)a_in);
            atomicAdd(&g_acc[1], (double)a_out);
            atomicAdd(&g_acc[2], (double)a_el);
        }
    }
}

__global__ void ace_finalize(float* out) {
    // region = MIU*|sum_in| + |sum_out|; elastica = ALPHA*N + sum(curv^2 * length)
    const double alpha_total = ALPHA * (double)NTOT;
    const double r = fabs(g_acc[0]) + fabs(g_acc[1]) + g_acc[2] + alpha_total;
    out[0] = (float)r;
}

extern "C" void kernel_launch(void* const* d_in, const int* in_sizes, int n_in,
                              void* d_out, int out_size) {
    const float* y_pred = (const float*)d_in[0];
    const float* y_true = (const float*)d_in[1];
    float* out = (float*)d_out;

    ace_zero<<<1, 1>>>();
    ace_main<<<NTOT / 256, 256>>>(y_pred, y_true);
    ace_finalize<<<1, 1>>>(out);
}

// round 3
// speedup vs baseline: 3.4940x; 3.4940x over previous
#include <cuda_runtime.h>
#include <math.h>

// Problem constants: shape (2,3,128,128,128) fp32
#define NTOT   (12582912)      // 6 << 21
#define NROWS  (98304)         // 6*128*128 rows of 128 x-values
#define ALPHA  0.001
#define EPSF   1e-8f

static __device__ double g_acc[3];   // [0]=region_in, [1]=region_out, [2]=elastica(curv part)

__global__ void ace_zero() {
    g_acc[0] = 0.0; g_acc[1] = 0.0; g_acc[2] = 0.0;
}

// Each warp handles one (vol, z, y) row of 128 x-values: 32 lanes x float4.
// 9 input rows per output row; x-neighbors via float4 internals + lane shuffles.
__global__ __launch_bounds__(256) void ace_main(
    const float* __restrict__ yp, const float* __restrict__ yt)
{
    const unsigned FULL = 0xFFFFFFFFu;
    const int wid  = threadIdx.x >> 5;
    const int lane = threadIdx.x & 31;
    const int r = blockIdx.x * 8 + wid;           // row id, 0..NROWS-1

    const int y   = r & 127;
    const int z   = (r >> 7) & 127;
    const int vol = r >> 14;

    const int ym = y > 0   ? y - 1 : 0;
    const int yq = y < 127 ? y + 1 : 127;
    const int zm = z > 0   ? z - 1 : 0;
    const int zq = z < 127 ? z + 1 : 127;

    const size_t vb = (size_t)vol << 21;
    #define ROW(zz,yy) (const float4*)(yp + vb + ((size_t)(zz) << 14) + ((yy) << 7))

    const float4 c4  = __ldg(ROW(z , y ) + lane);
    const float4 zm4 = __ldg(ROW(zm, y ) + lane);
    const float4 zp4 = __ldg(ROW(zq, y ) + lane);
    const float4 ym4 = __ldg(ROW(z , ym) + lane);
    const float4 yp4 = __ldg(ROW(z , yq) + lane);
    const float4 mm4 = __ldg(ROW(zm, ym) + lane);   // (z-1, y-1)
    const float4 mp4 = __ldg(ROW(zm, yq) + lane);   // (z-1, y+1)
    const float4 pm4 = __ldg(ROW(zq, ym) + lane);   // (z+1, y-1)
    const float4 pp4 = __ldg(ROW(zq, yq) + lane);   // (z+1, y+1)
    const float4 t4  = __ldg((const float4*)(yt + vb + ((size_t)z << 14) + (y << 7)) + lane);
    #undef ROW

    // 6-wide x windows (left neighbor, 4 values, right neighbor) for the 5
    // rows that need x+-1; clamp at the row ends.
    #define MK6(A, V)                                                   \
        float A[6];                                                     \
        A[1] = V.x; A[2] = V.y; A[3] = V.z; A[4] = V.w;                 \
        {   float L = __shfl_up_sync(FULL, V.w, 1);                     \
            float R = __shfl_down_sync(FULL, V.x, 1);                   \
            A[0] = (lane == 0)  ? V.x : L;                              \
            A[5] = (lane == 31) ? V.w : R; }

    MK6(cc, c4)
    MK6(azm, zm4)
    MK6(azp, zp4)
    MK6(aym, ym4)
    MK6(ayp, yp4)
    #undef MK6

    const float amm[4] = {mm4.x, mm4.y, mm4.z, mm4.w};
    const float amp[4] = {mp4.x, mp4.y, mp4.z, mp4.w};
    const float apm[4] = {pm4.x, pm4.y, pm4.z, pm4.w};
    const float app[4] = {pp4.x, pp4.y, pp4.z, pp4.w};
    const float tt [4] = {t4.x,  t4.y,  t4.z,  t4.w};

    float a_in = 0.f, a_out = 0.f, a_el = 0.f;

    #pragma unroll
    for (int j = 0; j < 4; j++) {
        const float uc  = cc[j + 1];
        const float uxm = cc[j];
        const float uxp = cc[j + 2];
        const float uzm = azm[j + 1];
        const float uzp = azp[j + 1];
        const float uym = aym[j + 1];
        const float uyp = ayp[j + 1];

        // first derivatives (i=z, j=y, k=x)
        const float ci = 0.5f * (uzp - uzm);
        const float cj = 0.5f * (uyp - uym);
        const float ck = 0.5f * (uxp - uxm);

        // second derivatives (clamped form is exact at boundaries)
        const float cii = uzp + uzm - 2.f * uc;
        const float cjj = uyp + uym - 2.f * uc;
        const float ckk = uxp + uxm - 2.f * uc;

        // mixed derivatives (mixed(c)[i] = c[clamp(i+1)] - c[clamp(i-1)])
        const float cij = 0.5f * ((app[j] - amp[j]) - (apm[j] - amm[j]));
        const float cik = 0.5f * ((azp[j + 2] - azm[j + 2]) - (azp[j] - azm[j]));
        const float cjk = 0.5f * ((ayp[j + 2] - aym[j + 2]) - (ayp[j] - aym[j]));

        const float ci2 = ci * ci, cj2 = cj * cj, ck2 = ck * ck;
        const float s = ci2 + cj2 + ck2;
        const float length = sqrtf(EPSF + s);
        const float curv = (1.f + ci2 + cj2) * ckk
                         + (1.f + cj2 + ck2) * cii
                         + (1.f + ci2 + ck2) * cjj
                         - 2.f * cik * cjk * cij;
        const float denom = sqrtf(1.f + s) + EPSF;
        const float q = __fdividef(curv, denom);
        a_el = fmaf(q * q, length, a_el);       // BETA=1; ALPHA added analytically

        const float t = tt[j];
        const float tm1 = t - 1.f;
        a_in  = fmaf(uc, tm1 * tm1, a_in);
        a_out = fmaf(1.f - uc, t * t, a_out);
    }

    // ---- block reduction (3 accumulators) ----
    #pragma unroll
    for (int o = 16; o > 0; o >>= 1) {
        a_in  += __shfl_down_sync(FULL, a_in,  o);
        a_out += __shfl_down_sync(FULL, a_out, o);
        a_el  += __shfl_down_sync(FULL, a_el,  o);
    }

    __shared__ float s_in[8], s_out[8], s_el[8];
    if (lane == 0) { s_in[wid] = a_in; s_out[wid] = a_out; s_el[wid] = a_el; }
    __syncthreads();

    if (wid == 0) {
        a_in  = (lane < 8) ? s_in[lane]  : 0.f;
        a_out = (lane < 8) ? s_out[lane] : 0.f;
        a_el  = (lane < 8) ? s_el[lane]  : 0.f;
        #pragma unroll
        for (int o = 4; o > 0; o >>= 1) {
            a_in  += __shfl_down_sync(FULL, a_in,  o);
            a_out += __shfl_down_sync(FULL, a_out, o);
            a_el  += __shfl_down_sync(FULL, a_el,  o);
        }
        if (lane == 0) {
            atomicAdd(&g_acc[0], (double)a_in);
            atomicAdd(&g_acc[1], (double)a_out);
            atomicAdd(&g_acc[2], (double)a_el);
        }
    }
}

__global__ void ace_finalize(float* out) {
    const double alpha_total = ALPHA * (double)NTOT;
    const double rsum = fabs(g_acc[0]) + fabs(g_acc[1]) + g_acc[2] + alpha_total;
    out[0] = (float)rsum;
}

extern "C" void kernel_launch(void* const* d_in, const int* in_sizes, int n_in,
                              void* d_out, int out_size) {
    const float* y_pred = (const float*)d_in[0];
    const float* y_true = (const float*)d_in[1];
    float* out = (float*)d_out;

    ace_zero<<<1, 1>>>();
    ace_main<<<NROWS / 8, 256>>>(y_pred, y_true);
    ace_finalize<<<1, 1>>>(out);
}